// round 12
// baseline (speedup 1.0000x reference)
#include <cuda_runtime.h>
#include <math.h>

#define S   512
#define BATCH 32
#define D   512
#define H   512
#define V   64
#define G4  2048   // 4*H
#define NC  32     // CTAs per direction in lstm kernel

// ---------------- scratch (static device globals; no allocation) ----------------
__device__ float g_x0[S * D];                 // batch-0 embeddings
__device__ float g_gin0[2][S * G4];           // layer0 input projections (+biases), per dir
__device__ float g_gin1[2][S * G4];           // layer1 input projections (+biases), per dir
// tagged h exchange AND history: word = (u32 tag << 32) | f32 bits.
// Slot s expected tag at read time == iteration t; producer writes tag t+1.
// logits reads the low 32 bits after the lstm kernel completes.
__device__ unsigned long long g_Tf0[(S + 1) * H];
__device__ unsigned long long g_Tb0[(S + 1) * H];
__device__ unsigned long long g_Tf1[(S + 1) * H];
__device__ unsigned long long g_Tb1[(S + 1) * H];
__device__ float g_xcat[S * 2 * H];           // layer1 input [S,1024], written by lstm layer0
__device__ float g_logits[S * V];

// MUFU tanh (sm_75+), ~1e-5 abs err (validated rel_err=0 rounds 8-11);
// sigmoid via tanh identity: sigma(x) = 0.5 + 0.5*tanh(x/2)
__device__ __forceinline__ float tanha(float x) {
    float y;
    asm("tanh.approx.f32 %0, %1;" : "=f"(y) : "f"(x));
    return y;
}
__device__ __forceinline__ float fsigmoid(float x) {
    return fmaf(tanha(0.5f * x), 0.5f, 0.5f);
}
__device__ __forceinline__ float lo32(unsigned long long u) {
    return __uint_as_float((unsigned)u);
}

// ---------------- fused init (zero tags) + embedding gather (batch 0) ----------------
__global__ void init_embed_kernel(const int* __restrict__ src, const float* __restrict__ emb) {
    int s = blockIdx.x;          // 512 CTAs, 256 threads
    int tid = threadIdx.x;

    if (tid < 128) {
        int tok = src[s * BATCH];   // batch element 0
        const float4* e = (const float4*)(emb + (size_t)tok * D);
        float4* x = (float4*)(g_x0 + (size_t)s * D);
        x[tid] = e[tid];
    }

    const int n = (S + 1) * H;
    int stride = gridDim.x * blockDim.x;
    for (int i = s * blockDim.x + tid; i < n; i += stride) {
        g_Tf0[i] = 0ull; g_Tb0[i] = 0ull; g_Tf1[i] = 0ull; g_Tb1[i] = 0ull;
    }
}

// ---------------- fp32 GEMM (scalar FFMA, R9-exact):  C = A @ B^T + b1 + b2 ----------------
// M = S = 512, N = G4 = 2048. blockIdx.z = direction.
__global__ __launch_bounds__(256) void gemm_kernel(int layer,
                                                   const float* __restrict__ Bmat,
                                                   const float* __restrict__ bias1,
                                                   const float* __restrict__ bias2,
                                                   int K) {
    const int N = G4;
    int z = blockIdx.z;
    const float* A = (layer == 0) ? g_x0 : g_xcat;
    float* C = (layer == 0) ? g_gin0[z] : g_gin1[z];
    const float* Bp = Bmat + (size_t)z * N * K;
    const float* b1 = bias1 + (size_t)z * N;
    const float* b2 = bias2 + (size_t)z * N;

    __shared__ float As[8][128];
    __shared__ float Bs[8][128];

    int tid = threadIdx.x;
    int mBase = blockIdx.y * 128;
    int nBase = blockIdx.x * 128;
    int lr = tid >> 1;
    int lc = (tid & 1) * 4;
    int tx = tid & 15;
    int ty = tid >> 4;

    float acc[8][8];
#pragma unroll
    for (int i = 0; i < 8; i++)
#pragma unroll
        for (int j = 0; j < 8; j++) acc[i][j] = 0.f;

    const float* Aload = A + (size_t)(mBase + lr) * K + lc;
    const float* Bload = Bp + (size_t)(nBase + lr) * K + lc;

    for (int k0 = 0; k0 < K; k0 += 8) {
        float4 av = *(const float4*)(Aload + k0);
        float4 bv = *(const float4*)(Bload + k0);
        __syncthreads();
        As[lc + 0][lr] = av.x; As[lc + 1][lr] = av.y; As[lc + 2][lr] = av.z; As[lc + 3][lr] = av.w;
        Bs[lc + 0][lr] = bv.x; Bs[lc + 1][lr] = bv.y; Bs[lc + 2][lr] = bv.z; Bs[lc + 3][lr] = bv.w;
        __syncthreads();
#pragma unroll
        for (int kk = 0; kk < 8; kk++) {
            float a[8], b[8];
            *(float4*)(a) = *(float4*)&As[kk][ty * 8];
            *(float4*)(a + 4) = *(float4*)&As[kk][ty * 8 + 4];
            *(float4*)(b) = *(float4*)&Bs[kk][tx * 8];
            *(float4*)(b + 4) = *(float4*)&Bs[kk][tx * 8 + 4];
#pragma unroll
            for (int i = 0; i < 8; i++)
#pragma unroll
                for (int j = 0; j < 8; j++)
                    acc[i][j] = fmaf(a[i], b[j], acc[i][j]);
        }
    }

    float bs[8];
#pragma unroll
    for (int j = 0; j < 8; j++)
        bs[j] = b1[nBase + tx * 8 + j] + b2[nBase + tx * 8 + j];

#pragma unroll
    for (int i = 0; i < 8; i++) {
        float* crow = C + (size_t)(mBase + ty * 8 + i) * N + nBase + tx * 8;
        float4 o0 = make_float4(acc[i][0] + bs[0], acc[i][1] + bs[1], acc[i][2] + bs[2], acc[i][3] + bs[3]);
        float4 o1 = make_float4(acc[i][4] + bs[4], acc[i][5] + bs[5], acc[i][6] + bs[6], acc[i][7] + bs[7]);
        ((float4*)crow)[0] = o0;
        ((float4*)crow)[1] = o1;
    }
}

// ---------------- persistent BiLSTM layer: tagged-word handshake, pipelined poll ----------------
// grid = 2*NC CTAs, 512 threads. CTA owns 16 h-outputs (64 gate rows).
// Thread: row r = tid>>3 (0..63), chunk c = tid&7 (interleaved 16B columns 8i+c).
// Producers (warp-0 threads 0..15) emit ONE tagged 8B word each, coalesced 128B;
// the store is the release. 256 pollers, one 16B pair each, spin loop software-
// pipelined with 2 loads in flight (halves sampling period). Layer 0 producers
// also write h into g_xcat (replaces pack kernel).
__global__ __launch_bounds__(512) void lstm_kernel(int layer, const float* __restrict__ Whh) {
    int dir = (blockIdx.x >= NC) ? 1 : 0;
    int cb = blockIdx.x & (NC - 1);
    int base = cb * 16;

    const float* Gin = (layer == 0) ? g_gin0[dir] : g_gin1[dir];
    unsigned long long* Tg = (layer == 0) ? (dir ? g_Tb0 : g_Tf0) : (dir ? g_Tb1 : g_Tf1);
    const float* W = Whh + (size_t)dir * G4 * H;

    int tid = threadIdx.x;
    int r = tid >> 3;          // gate-row within CTA (0..63)
    int c = tid & 7;           // 16B column chunk (0..7)
    int gate = r >> 4;         // 0..3  (i,f,g,o)
    int jj = r & 15;           // h-output within CTA
    int rowg = gate * H + base + jj;

    // 64 weight floats in registers as f32x2 pairs
    ulonglong2 w[16];
    const ulonglong2* wrow = (const ulonglong2*)(W + (size_t)rowg * H);
#pragma unroll
    for (int i = 0; i < 16; i++) w[i] = wrow[8 * i + c];

    __shared__ ulonglong2 hs4[128];     // previous h (512 floats)
    __shared__ float gsum[64];
    __shared__ float gadd[2][64];
    float2* hsf2 = (float2*)hs4;
    float creg = 0.f;                   // cell state (tid<16)

    for (int t = 0; t < S; t++) {
        int tt = dir ? (S - 1 - t) : t;
        int ridx = dir ? (tt + 1) : tt;   // read slot
        int widx = dir ? tt : (tt + 1);   // write slot

        // input projection (independent of h) — issue before the poll
        float gv = 0.f;
        if (tid < 64)
            gv = Gin[(size_t)tt * G4 + (tid >> 4) * H + base + (tid & 15)];

        // pipelined poll: 2 volatile loads in flight; check the older one.
        // Sampling period ~ RT/2 instead of RT. Exit never waits on the
        // younger in-flight load.
        if (tid < 256) {
            const unsigned long long* tp = Tg + (size_t)ridx * H + 2 * tid;
            unsigned exp = (unsigned)t;
            unsigned long long a0, a1, b0, b1;
            asm volatile("ld.volatile.global.v2.u64 {%0,%1}, [%2];"
                         : "=l"(a0), "=l"(a1) : "l"(tp));
            asm volatile("ld.volatile.global.v2.u64 {%0,%1}, [%2];"
                         : "=l"(b0), "=l"(b1) : "l"(tp));
            while ((unsigned)(a0 >> 32) != exp || (unsigned)(a1 >> 32) != exp) {
                a0 = b0; a1 = b1;
                asm volatile("ld.volatile.global.v2.u64 {%0,%1}, [%2];"
                             : "=l"(b0), "=l"(b1) : "l"(tp));
            }
            hsf2[tid] = make_float2(lo32(a0), lo32(a1));
        }
        if (tid < 64) gadd[t & 1][tid] = gv;
        __syncthreads();   // B: hs4 + gadd ready

        // dot: 16 16B chunks via packed fma.rn.f32x2 (32 FFMA2/thread)
        unsigned long long a0 = 0ull, a1 = 0ull, a2 = 0ull, a3 = 0ull;
#pragma unroll
        for (int i = 0; i < 16; i += 2) {
            ulonglong2 h0 = hs4[8 * (i + 0) + c];
            ulonglong2 h1 = hs4[8 * (i + 1) + c];
            asm("fma.rn.f32x2 %0, %1, %2, %0;" : "+l"(a0) : "l"(w[i + 0].x), "l"(h0.x));
            asm("fma.rn.f32x2 %0, %1, %2, %0;" : "+l"(a1) : "l"(w[i + 0].y), "l"(h0.y));
            asm("fma.rn.f32x2 %0, %1, %2, %0;" : "+l"(a2) : "l"(w[i + 1].x), "l"(h1.x));
            asm("fma.rn.f32x2 %0, %1, %2, %0;" : "+l"(a3) : "l"(w[i + 1].y), "l"(h1.y));
        }
        float2 f0 = *(float2*)&a0, f1 = *(float2*)&a1, f2 = *(float2*)&a2, f3 = *(float2*)&a3;
        float acc = ((f0.x + f0.y) + (f1.x + f1.y)) + ((f2.x + f2.y) + (f3.x + f3.y));
        acc += __shfl_xor_sync(0xffffffffu, acc, 1);
        acc += __shfl_xor_sync(0xffffffffu, acc, 2);
        acc += __shfl_xor_sync(0xffffffffu, acc, 4);
        if (c == 0) gsum[r] = acc;
        __syncthreads();   // C: gsum ready

        if (tid < 16) {
            float gi = gsum[tid] + gadd[t & 1][tid];
            float gf = gsum[16 + tid] + gadd[t & 1][16 + tid];
            float gg = gsum[32 + tid] + gadd[t & 1][32 + tid];
            float go = gsum[48 + tid] + gadd[t & 1][48 + tid];
            float si = fsigmoid(gi);
            float sf = fsigmoid(gf);
            float so = fsigmoid(go);
            creg = sf * creg + si * tanha(gg);
            float hh = so * tanha(creg);
            // tagged release store first (coalesced 128B across tid 0..15)
            unsigned long long tw = ((unsigned long long)(unsigned)(t + 1) << 32)
                                  | (unsigned long long)__float_as_uint(hh);
            __stcg(&Tg[(size_t)widx * H + base + tid], tw);
            // layer 0: also write xcat row tt (replaces pack kernel);
            // issued after the release, does not delay it
            if (layer == 0)
                __stcg(&g_xcat[(size_t)tt * 1024 + dir * 512 + base + tid], hh);
        }
        // no barrier D: cross-iteration smem races excluded by B and C
    }
}

// ---------------- logits[t,v] = zcat[t] . Wout[v] + bout[v] ----------------
__global__ __launch_bounds__(256) void logits_kernel(const float* __restrict__ Wout,
                                                     const float* __restrict__ bout) {
    int t = blockIdx.x;
    int tid = threadIdx.x;
    __shared__ float z[1024];
    __shared__ float ps[256];
    if (tid < 128) {
        const ulonglong2* p = (const ulonglong2*)(g_Tf1 + (size_t)(t + 1) * H + 4 * tid);
        ulonglong2 q0 = p[0], q1 = p[1];
        ((float4*)z)[tid] = make_float4(lo32(q0.x), lo32(q0.y), lo32(q1.x), lo32(q1.y));
    } else {
        const ulonglong2* p = (const ulonglong2*)(g_Tb1 + (size_t)t * H + 4 * (tid - 128));
        ulonglong2 q0 = p[0], q1 = p[1];
        ((float4*)z)[tid] = make_float4(lo32(q0.x), lo32(q0.y), lo32(q1.x), lo32(q1.y));
    }
    __syncthreads();

    int v = tid & 63, p = tid >> 6;   // 4 threads per output
    const float4* wr = (const float4*)(Wout + (size_t)v * 1024 + p * 256);
    const float4* zz = (const float4*)(z + p * 256);
    float s0 = 0.f, s1 = 0.f, s2 = 0.f, s3 = 0.f;
#pragma unroll
    for (int i = 0; i < 64; i += 4) {
        float4 a0 = wr[i + 0], b0 = zz[i + 0];
        float4 a1 = wr[i + 1], b1 = zz[i + 1];
        float4 a2 = wr[i + 2], b2 = zz[i + 2];
        float4 a3 = wr[i + 3], b3 = zz[i + 3];
        s0 = fmaf(a0.x, b0.x, fmaf(a0.y, b0.y, fmaf(a0.z, b0.z, fmaf(a0.w, b0.w, s0))));
        s1 = fmaf(a1.x, b1.x, fmaf(a1.y, b1.y, fmaf(a1.z, b1.z, fmaf(a1.w, b1.w, s1))));
        s2 = fmaf(a2.x, b2.x, fmaf(a2.y, b2.y, fmaf(a2.z, b2.z, fmaf(a2.w, b2.w, s2))));
        s3 = fmaf(a3.x, b3.x, fmaf(a3.y, b3.y, fmaf(a3.z, b3.z, fmaf(a3.w, b3.w, s3))));
    }
    ps[tid] = (s0 + s1) + (s2 + s3);
    __syncthreads();
    if (tid < 64)
        g_logits[t * 64 + tid] = ps[tid] + ps[64 + tid] + ps[128 + tid] + ps[192 + tid] + bout[tid];
}

// ---------------- Viterbi (single CTA, serial over time) ----------------
__global__ __launch_bounds__(256) void viterbi_kernel(const float* __restrict__ trans,
                                                      float* __restrict__ path) {
    __shared__ float ds[2][64];
    __shared__ unsigned char bp[511 * 64];

    int tid = threadIdx.x;
    int lane = tid & 31;
    int w = tid >> 5;
    int j = w * 8 + (lane >> 2);
    int p = lane & 3;

    float tr[16];
#pragma unroll
    for (int s = 0; s < 16; s++)
        tr[s] = trans[(p * 16 + s) * 64 + j];

    if (p == 0) ds[0][j] = g_logits[j];
    __syncthreads();

    for (int t = 1; t < S; t++) {
        int rd = (t - 1) & 1, wr = t & 1;
        float lt = g_logits[t * 64 + j];
        float best = (ds[rd][p * 16] + tr[0]) + lt;
        int bi = p * 16;
#pragma unroll
        for (int s = 1; s < 16; s++) {
            int i = p * 16 + s;
            float sc = (ds[rd][i] + tr[s]) + lt;   // same op order as reference
            if (sc > best) { best = sc; bi = i; }
        }
#pragma unroll
        for (int off = 1; off < 4; off <<= 1) {
            float ov = __shfl_xor_sync(0xffffffffu, best, off);
            int oi = __shfl_xor_sync(0xffffffffu, bi, off);
            if (ov > best || (ov == best && oi < bi)) { best = ov; bi = oi; }
        }
        if (p == 0) {
            ds[wr][j] = best;
            bp[(t - 1) * 64 + j] = (unsigned char)bi;
        }
        __syncthreads();
    }

    if (tid == 0) {
        float best = ds[1][0];
        int last = 0;
        for (int i = 1; i < 64; i++) {
            if (ds[1][i] > best) { best = ds[1][i]; last = i; }
        }
        path[S - 1] = (float)last;
        for (int t = S - 2; t >= 0; t--) {
            last = bp[t * 64 + last];
            path[t] = (float)last;
        }
    }
}

// ---------------- launch ----------------
extern "C" void kernel_launch(void* const* d_in, const int* in_sizes, int n_in,
                              void* d_out, int out_size) {
    int ie = 2;
    for (int i = 1; i < n_in; i++) {
        if (in_sizes[i] == 30000 * 512) { ie = i; break; }
    }

    const int* src = (const int*)d_in[0];
    const float* emb = (const float*)d_in[ie];
    const float* Wih0 = (const float*)d_in[ie + 1];
    const float* Whh0 = (const float*)d_in[ie + 2];
    const float* bih0 = (const float*)d_in[ie + 3];
    const float* bhh0 = (const float*)d_in[ie + 4];
    const float* Wih1 = (const float*)d_in[ie + 5];
    const float* Whh1 = (const float*)d_in[ie + 6];
    const float* bih1 = (const float*)d_in[ie + 7];
    const float* bhh1 = (const float*)d_in[ie + 8];
    const float* Wout = (const float*)d_in[ie + 9];
    const float* bout = (const float*)d_in[ie + 10];
    const float* trans = (const float*)d_in[ie + 11];
    float* path = (float*)d_out;

    init_embed_kernel<<<S, 256>>>(src, emb);

    dim3 gg(G4 / 128, S / 128, 2);
    gemm_kernel<<<gg, 256>>>(0, Wih0, bih0, bhh0, D);
    lstm_kernel<<<2 * NC, 512>>>(0, Whh0);
    gemm_kernel<<<gg, 256>>>(1, Wih1, bih1, bhh1, 2 * H);
    lstm_kernel<<<2 * NC, 512>>>(1, Whh1);
    logits_kernel<<<S, 256>>>(Wout, bout);
    viterbi_kernel<<<1, 256>>>(trans, path);
}

// round 13
// speedup vs baseline: 1.1249x; 1.1249x over previous
#include <cuda_runtime.h>
#include <math.h>

#define S   512
#define BATCH 32
#define D   512
#define H   512
#define V   64
#define G4  2048   // 4*H
#define NC  32     // CTAs per direction in lstm kernel

// ---------------- scratch (static device globals; no allocation) ----------------
__device__ float g_x0[S * D];                 // batch-0 embeddings
__device__ float g_gin0[2][S * G4];           // layer0 input projections (+biases), per dir
__device__ float g_gin1[2][S * G4];           // layer1 input projections (+biases), per dir
__device__ float g_Hf0[(S + 1) * H];          // plain h history (read by pack/logits)
__device__ float g_Hb0[(S + 1) * H];
__device__ float g_Hf1[(S + 1) * H];
__device__ float g_Hb1[(S + 1) * H];
// tagged h exchange: word = (u32 tag << 32) | f32 bits. Slot s expected tag at
// read time == iteration t; producer writes tag t+1 into its widx slot.
__device__ unsigned long long g_Tf0[(S + 1) * H];
__device__ unsigned long long g_Tb0[(S + 1) * H];
__device__ unsigned long long g_Tf1[(S + 1) * H];
__device__ unsigned long long g_Tb1[(S + 1) * H];
__device__ float g_xcat[S * 2 * H];           // layer1 input [S,1024]
__device__ float g_logits[S * V];

// MUFU tanh (sm_75+), ~1e-5 abs err (validated rel_err=0 in rounds 8-12);
// sigmoid via tanh identity: sigma(x) = 0.5 + 0.5*tanh(x/2)
__device__ __forceinline__ float tanha(float x) {
    float y;
    asm("tanh.approx.f32 %0, %1;" : "=f"(y) : "f"(x));
    return y;
}
__device__ __forceinline__ float fsigmoid(float x) {
    return fmaf(tanha(0.5f * x), 0.5f, 0.5f);
}
__device__ __forceinline__ float lo32(unsigned long long u) {
    return __uint_as_float((unsigned)u);
}

// ---------------- init: zero all tag words ----------------
__global__ void init_kernel() {
    const int n = (S + 1) * H;
    int stride = gridDim.x * blockDim.x;
    int i0 = blockIdx.x * blockDim.x + threadIdx.x;
    for (int i = i0; i < n; i += stride) {
        g_Tf0[i] = 0ull; g_Tb0[i] = 0ull; g_Tf1[i] = 0ull; g_Tb1[i] = 0ull;
    }
}

// ---------------- embedding gather (batch 0 only) ----------------
__global__ void embed_kernel(const int* __restrict__ src, const float* __restrict__ emb) {
    int s = blockIdx.x;
    int tok = src[s * BATCH];   // batch element 0
    const float4* e = (const float4*)(emb + (size_t)tok * D);
    float4* x = (float4*)(g_x0 + (size_t)s * D);
    x[threadIdx.x] = e[threadIdx.x];   // 128 threads * float4 = 512 floats
}

// ---------------- fp32 GEMM (natural-pair f32x2):  C = A @ B^T + b1 + b2 ----------------
// M = S = 512, N = G4 = 2048. blockIdx.z = direction.
// A row-pairs come packed for free from contiguous As rows (LDS.128 = 2 f32x2
// pairs); only B is duplicated (8 mov.b64/kk on the ALU pipe, hidden under
// FFMA2). Per-element accumulation order identical to scalar (lo/hi lanes are
// independent fmas in the same k-order).
__global__ __launch_bounds__(256) void gemm_kernel(int layer,
                                                   const float* __restrict__ Bmat,
                                                   const float* __restrict__ bias1,
                                                   const float* __restrict__ bias2,
                                                   int K) {
    const int N = G4;
    int z = blockIdx.z;
    const float* A = (layer == 0) ? g_x0 : g_xcat;
    float* C = (layer == 0) ? g_gin0[z] : g_gin1[z];
    const float* Bp = Bmat + (size_t)z * N * K;
    const float* b1 = bias1 + (size_t)z * N;
    const float* b2 = bias2 + (size_t)z * N;

    __shared__ float As[8][128];
    __shared__ float Bs[8][128];

    int tid = threadIdx.x;
    int mBase = blockIdx.y * 128;
    int nBase = blockIdx.x * 128;
    int lr = tid >> 1;
    int lc = (tid & 1) * 4;
    int tx = tid & 15;
    int ty = tid >> 4;

    // acc2[rp][j] = (C[ty*8+2rp][j], C[ty*8+2rp+1][j]) packed f32x2
    unsigned long long acc2[4][8];
#pragma unroll
    for (int i = 0; i < 4; i++)
#pragma unroll
        for (int j = 0; j < 8; j++) acc2[i][j] = 0ull;

    const float* Aload = A + (size_t)(mBase + lr) * K + lc;
    const float* Bload = Bp + (size_t)(nBase + lr) * K + lc;

    for (int k0 = 0; k0 < K; k0 += 8) {
        float4 av = *(const float4*)(Aload + k0);
        float4 bv = *(const float4*)(Bload + k0);
        __syncthreads();
        As[lc + 0][lr] = av.x; As[lc + 1][lr] = av.y; As[lc + 2][lr] = av.z; As[lc + 3][lr] = av.w;
        Bs[lc + 0][lr] = bv.x; Bs[lc + 1][lr] = bv.y; Bs[lc + 2][lr] = bv.z; Bs[lc + 3][lr] = bv.w;
        __syncthreads();
#pragma unroll
        for (int kk = 0; kk < 8; kk++) {
            // A row-pairs: rows are contiguous in As → natural f32x2 packing
            ulonglong2 a01 = *(ulonglong2*)&As[kk][ty * 8];
            ulonglong2 a23 = *(ulonglong2*)&As[kk][ty * 8 + 4];
            unsigned long long ap0 = a01.x, ap1 = a01.y, ap2 = a23.x, ap3 = a23.y;
            float b[8];
            *(float4*)(b) = *(float4*)&Bs[kk][tx * 8];
            *(float4*)(b + 4) = *(float4*)&Bs[kk][tx * 8 + 4];
            unsigned long long bb[8];
#pragma unroll
            for (int j = 0; j < 8; j++)
                asm("mov.b64 %0, {%1, %1};" : "=l"(bb[j]) : "f"(b[j]));
#pragma unroll
            for (int j = 0; j < 8; j++) {
                asm("fma.rn.f32x2 %0, %1, %2, %0;" : "+l"(acc2[0][j]) : "l"(ap0), "l"(bb[j]));
                asm("fma.rn.f32x2 %0, %1, %2, %0;" : "+l"(acc2[1][j]) : "l"(ap1), "l"(bb[j]));
                asm("fma.rn.f32x2 %0, %1, %2, %0;" : "+l"(acc2[2][j]) : "l"(ap2), "l"(bb[j]));
                asm("fma.rn.f32x2 %0, %1, %2, %0;" : "+l"(acc2[3][j]) : "l"(ap3), "l"(bb[j]));
            }
        }
    }

    float bs[8];
#pragma unroll
    for (int j = 0; j < 8; j++)
        bs[j] = b1[nBase + tx * 8 + j] + b2[nBase + tx * 8 + j];

    float o[8][8];
#pragma unroll
    for (int rp = 0; rp < 4; rp++)
#pragma unroll
        for (int j = 0; j < 8; j++)
            asm("mov.b64 {%0, %1}, %2;"
                : "=f"(o[2 * rp][j]), "=f"(o[2 * rp + 1][j]) : "l"(acc2[rp][j]));

#pragma unroll
    for (int i = 0; i < 8; i++) {
        float* crow = C + (size_t)(mBase + ty * 8 + i) * N + nBase + tx * 8;
        float4 o0 = make_float4(o[i][0] + bs[0], o[i][1] + bs[1], o[i][2] + bs[2], o[i][3] + bs[3]);
        float4 o1 = make_float4(o[i][4] + bs[4], o[i][5] + bs[5], o[i][6] + bs[6], o[i][7] + bs[7]);
        ((float4*)crow)[0] = o0;
        ((float4*)crow)[1] = o1;
    }
}

// ---------------- persistent BiLSTM layer: tagged-word handshake (R9-exact, 1812us config) ----------------
// grid = 2*NC CTAs, 512 threads. CTA owns 16 h-outputs (64 gate rows).
// Thread: row r = tid>>3 (0..63), chunk c = tid&7 (interleaved 16B columns 8i+c).
// Producers: warp-0 threads 0..15 store 16 tagged 8B words COALESCED; the store
// is the release. Exactly 256 pollers, one 16B pair each, simple spin loop.
__global__ __launch_bounds__(512) void lstm_kernel(int layer, const float* __restrict__ Whh) {
    int dir = (blockIdx.x >= NC) ? 1 : 0;
    int cb = blockIdx.x & (NC - 1);
    int base = cb * 16;

    const float* Gin = (layer == 0) ? g_gin0[dir] : g_gin1[dir];
    float* Hs = (layer == 0) ? (dir ? g_Hb0 : g_Hf0) : (dir ? g_Hb1 : g_Hf1);
    unsigned long long* Tg = (layer == 0) ? (dir ? g_Tb0 : g_Tf0) : (dir ? g_Tb1 : g_Tf1);
    const float* W = Whh + (size_t)dir * G4 * H;

    int tid = threadIdx.x;
    int r = tid >> 3;          // gate-row within CTA (0..63)
    int c = tid & 7;           // 16B column chunk (0..7)
    int gate = r >> 4;         // 0..3  (i,f,g,o)
    int jj = r & 15;           // h-output within CTA
    int rowg = gate * H + base + jj;

    // 64 weight floats in registers as f32x2 pairs
    ulonglong2 w[16];
    const ulonglong2* wrow = (const ulonglong2*)(W + (size_t)rowg * H);
#pragma unroll
    for (int i = 0; i < 16; i++) w[i] = wrow[8 * i + c];

    __shared__ ulonglong2 hs4[128];     // previous h (512 floats)
    __shared__ float gsum[64];
    __shared__ float gadd[2][64];
    float2* hsf2 = (float2*)hs4;
    float creg = 0.f;                   // cell state (tid<16)

    for (int t = 0; t < S; t++) {
        int tt = dir ? (S - 1 - t) : t;
        int ridx = dir ? (tt + 1) : tt;   // read slot
        int widx = dir ? tt : (tt + 1);   // write slot

        // input projection (independent of h) — issue before the poll
        float gv = 0.f;
        if (tid < 64)
            gv = Gin[(size_t)tt * G4 + (tid >> 4) * H + base + (tid & 15)];

        // poll tagged words: thread tid<256 owns one 16B pair
        if (tid < 256) {
            const unsigned long long* tp = Tg + (size_t)ridx * H + 2 * tid;
            unsigned exp = (unsigned)t;
            unsigned long long w0, w1;
            do {
                asm volatile("ld.volatile.global.v2.u64 {%0,%1}, [%2];"
                             : "=l"(w0), "=l"(w1) : "l"(tp));
            } while ((unsigned)(w0 >> 32) != exp || (unsigned)(w1 >> 32) != exp);
            hsf2[tid] = make_float2(lo32(w0), lo32(w1));
        }
        if (tid < 64) gadd[t & 1][tid] = gv;
        __syncthreads();   // B: hs4 + gadd ready

        // dot: 16 16B chunks via packed fma.rn.f32x2 (32 FFMA2/thread)
        unsigned long long a0 = 0ull, a1 = 0ull, a2 = 0ull, a3 = 0ull;
#pragma unroll
        for (int i = 0; i < 16; i += 2) {
            ulonglong2 h0 = hs4[8 * (i + 0) + c];
            ulonglong2 h1 = hs4[8 * (i + 1) + c];
            asm("fma.rn.f32x2 %0, %1, %2, %0;" : "+l"(a0) : "l"(w[i + 0].x), "l"(h0.x));
            asm("fma.rn.f32x2 %0, %1, %2, %0;" : "+l"(a1) : "l"(w[i + 0].y), "l"(h0.y));
            asm("fma.rn.f32x2 %0, %1, %2, %0;" : "+l"(a2) : "l"(w[i + 1].x), "l"(h1.x));
            asm("fma.rn.f32x2 %0, %1, %2, %0;" : "+l"(a3) : "l"(w[i + 1].y), "l"(h1.y));
        }
        float2 f0 = *(float2*)&a0, f1 = *(float2*)&a1, f2 = *(float2*)&a2, f3 = *(float2*)&a3;
        float acc = ((f0.x + f0.y) + (f1.x + f1.y)) + ((f2.x + f2.y) + (f3.x + f3.y));
        acc += __shfl_xor_sync(0xffffffffu, acc, 1);
        acc += __shfl_xor_sync(0xffffffffu, acc, 2);
        acc += __shfl_xor_sync(0xffffffffu, acc, 4);
        if (c == 0) gsum[r] = acc;
        __syncthreads();   // C: gsum ready

        if (tid < 16) {
            float gi = gsum[tid] + gadd[t & 1][tid];
            float gf = gsum[16 + tid] + gadd[t & 1][16 + tid];
            float gg = gsum[32 + tid] + gadd[t & 1][32 + tid];
            float go = gsum[48 + tid] + gadd[t & 1][48 + tid];
            float si = fsigmoid(gi);
            float sf = fsigmoid(gf);
            float so = fsigmoid(go);
            creg = sf * creg + si * tanha(gg);
            float hh = so * tanha(creg);
            // tagged word first (coalesced 128B across tid 0..15): the release
            unsigned long long tw = ((unsigned long long)(unsigned)(t + 1) << 32)
                                  | (unsigned long long)__float_as_uint(hh);
            __stcg(&Tg[(size_t)widx * H + base + tid], tw);
            // plain history for pack/logits (ordered by kernel boundary)
            __stcg(&Hs[(size_t)widx * H + base + tid], hh);
        }
        // no barrier D: cross-iteration smem races excluded by B and C
    }
}

// ---------------- pack layer1 input: xcat[t] = (hf0[t], hb0[t]) ----------------
__global__ void pack_kernel() {
    int t = blockIdx.x;
    int tid = threadIdx.x;   // 256
    float4* dst = (float4*)(g_xcat + (size_t)t * 1024);
    if (tid < 128) {
        dst[tid] = ((const float4*)(g_Hf0 + (size_t)(t + 1) * H))[tid];
    } else {
        dst[tid] = ((const float4*)(g_Hb0 + (size_t)t * H))[tid - 128];
    }
}

// ---------------- logits[t,v] = zcat[t] . Wout[v] + bout[v] ----------------
__global__ __launch_bounds__(256) void logits_kernel(const float* __restrict__ Wout,
                                                     const float* __restrict__ bout) {
    int t = blockIdx.x;
    int tid = threadIdx.x;
    __shared__ float z[1024];
    __shared__ float ps[256];
    if (tid < 128)
        ((float4*)z)[tid] = ((const float4*)(g_Hf1 + (size_t)(t + 1) * H))[tid];
    else
        ((float4*)z)[tid] = ((const float4*)(g_Hb1 + (size_t)t * H))[tid - 128];
    __syncthreads();

    int v = tid & 63, p = tid >> 6;   // 4 threads per output
    const float4* wr = (const float4*)(Wout + (size_t)v * 1024 + p * 256);
    const float4* zz = (const float4*)(z + p * 256);
    float s0 = 0.f, s1 = 0.f, s2 = 0.f, s3 = 0.f;
#pragma unroll
    for (int i = 0; i < 64; i += 4) {
        float4 a0 = wr[i + 0], b0 = zz[i + 0];
        float4 a1 = wr[i + 1], b1 = zz[i + 1];
        float4 a2 = wr[i + 2], b2 = zz[i + 2];
        float4 a3 = wr[i + 3], b3 = zz[i + 3];
        s0 = fmaf(a0.x, b0.x, fmaf(a0.y, b0.y, fmaf(a0.z, b0.z, fmaf(a0.w, b0.w, s0))));
        s1 = fmaf(a1.x, b1.x, fmaf(a1.y, b1.y, fmaf(a1.z, b1.z, fmaf(a1.w, b1.w, s1))));
        s2 = fmaf(a2.x, b2.x, fmaf(a2.y, b2.y, fmaf(a2.z, b2.z, fmaf(a2.w, b2.w, s2))));
        s3 = fmaf(a3.x, b3.x, fmaf(a3.y, b3.y, fmaf(a3.z, b3.z, fmaf(a3.w, b3.w, s3))));
    }
    ps[tid] = (s0 + s1) + (s2 + s3);
    __syncthreads();
    if (tid < 64)
        g_logits[t * 64 + tid] = ps[tid] + ps[64 + tid] + ps[128 + tid] + ps[192 + tid] + bout[tid];
}

// ---------------- Viterbi (single CTA, serial over time) ----------------
__global__ __launch_bounds__(256) void viterbi_kernel(const float* __restrict__ trans,
                                                      float* __restrict__ path) {
    __shared__ float ds[2][64];
    __shared__ unsigned char bp[511 * 64];

    int tid = threadIdx.x;
    int lane = tid & 31;
    int w = tid >> 5;
    int j = w * 8 + (lane >> 2);
    int p = lane & 3;

    float tr[16];
#pragma unroll
    for (int s = 0; s < 16; s++)
        tr[s] = trans[(p * 16 + s) * 64 + j];

    if (p == 0) ds[0][j] = g_logits[j];
    __syncthreads();

    for (int t = 1; t < S; t++) {
        int rd = (t - 1) & 1, wr = t & 1;
        float lt = g_logits[t * 64 + j];
        float best = (ds[rd][p * 16] + tr[0]) + lt;
        int bi = p * 16;
#pragma unroll
        for (int s = 1; s < 16; s++) {
            int i = p * 16 + s;
            float sc = (ds[rd][i] + tr[s]) + lt;   // same op order as reference
            if (sc > best) { best = sc; bi = i; }
        }
#pragma unroll
        for (int off = 1; off < 4; off <<= 1) {
            float ov = __shfl_xor_sync(0xffffffffu, best, off);
            int oi = __shfl_xor_sync(0xffffffffu, bi, off);
            if (ov > best || (ov == best && oi < bi)) { best = ov; bi = oi; }
        }
        if (p == 0) {
            ds[wr][j] = best;
            bp[(t - 1) * 64 + j] = (unsigned char)bi;
        }
        __syncthreads();
    }

    if (tid == 0) {
        float best = ds[1][0];
        int last = 0;
        for (int i = 1; i < 64; i++) {
            if (ds[1][i] > best) { best = ds[1][i]; last = i; }
        }
        path[S - 1] = (float)last;
        for (int t = S - 2; t >= 0; t--) {
            last = bp[t * 64 + last];
            path[t] = (float)last;
        }
    }
}

// ---------------- launch ----------------
extern "C" void kernel_launch(void* const* d_in, const int* in_sizes, int n_in,
                              void* d_out, int out_size) {
    int ie = 2;
    for (int i = 1; i < n_in; i++) {
        if (in_sizes[i] == 30000 * 512) { ie = i; break; }
    }

    const int* src = (const int*)d_in[0];
    const float* emb = (const float*)d_in[ie];
    const float* Wih0 = (const float*)d_in[ie + 1];
    const float* Whh0 = (const float*)d_in[ie + 2];
    const float* bih0 = (const float*)d_in[ie + 3];
    const float* bhh0 = (const float*)d_in[ie + 4];
    const float* Wih1 = (const float*)d_in[ie + 5];
    const float* Whh1 = (const float*)d_in[ie + 6];
    const float* bih1 = (const float*)d_in[ie + 7];
    const float* bhh1 = (const float*)d_in[ie + 8];
    const float* Wout = (const float*)d_in[ie + 9];
    const float* bout = (const float*)d_in[ie + 10];
    const float* trans = (const float*)d_in[ie + 11];
    float* path = (float*)d_out;

    init_kernel<<<256, 256>>>();
    embed_kernel<<<S, 128>>>(src, emb);

    dim3 gg(G4 / 128, S / 128, 2);
    gemm_kernel<<<gg, 256>>>(0, Wih0, bih0, bhh0, D);
    lstm_kernel<<<2 * NC, 512>>>(0, Whh0);
    pack_kernel<<<S, 256>>>();
    gemm_kernel<<<gg, 256>>>(1, Wih1, bih1, bhh1, 2 * H);
    lstm_kernel<<<2 * NC, 512>>>(1, Whh1);
    logits_kernel<<<S, 256>>>(Wout, bout);
    viterbi_kernel<<<1, 256>>>(trans, path);
}